// round 14
// baseline (speedup 1.0000x reference)
#include <cuda_runtime.h>
#include <cuda_fp16.h>
#include <cuda_bf16.h>
#include <cstdint>
#include <cstddef>

// ---------------- problem constants ----------------
#define Bb   2
#define Ss   2048
#define Hh   4096
#define NHh  32
#define HDd  128
#define QKVN 12288            // NH * 3 * HD
#define Mm   4096             // B * S

#define QSCALE 0.08838834764831845f

// ---------------- scratch (__device__ globals; no allocs allowed) ----------
__device__ __half g_attn[(size_t)Mm * Hh];     // flash out, A-frag half
__device__ __half g_hid [(size_t)Mm * Hh];     // hidden, A-frag half
__device__ __half g_w1t [(size_t)QKVN * Hh];   // w_qkv, B-frag half
__device__ __half g_w2t [(size_t)Hh * Hh];     // w_out, B-frag half
// flash-ready fragment buffers written by GEMM1:
__device__ uint4 g_qf[(size_t)NHh * 256 * 8 * 32];
__device__ uint2 g_kf[(size_t)NHh * 512 * 8 * 32];
__device__ uint2 g_vf[(size_t)NHh * 64 * 4 * 16 * 32];

// ---------------- helpers ----------------
__device__ __forceinline__ uint32_t smem_u32(const void* p) {
    uint32_t a;
    asm("{ .reg .u64 t; cvta.to.shared.u64 t, %1; cvt.u32.u64 %0, t; }" : "=r"(a) : "l"(p));
    return a;
}
__device__ __forceinline__ uint32_t pkh2(float a, float b) {
    __half2 h = __floats2half2_rn(a, b);
    return *(uint32_t*)&h;
}
#define CP_ASYNC16(dst, src) \
    asm volatile("cp.async.cg.shared.global [%0], [%1], 16;" :: "r"(dst), "l"(src))
#define CP_COMMIT() asm volatile("cp.async.commit_group;")

__device__ __forceinline__ void mma_f16(float* d, const uint32_t* a, const uint32_t* b) {
    asm volatile(
        "mma.sync.aligned.m16n8k16.row.col.f32.f16.f16.f32 "
        "{%0,%1,%2,%3}, {%4,%5,%6,%7}, {%8,%9}, {%0,%1,%2,%3};"
        : "+f"(d[0]), "+f"(d[1]), "+f"(d[2]), "+f"(d[3])
        : "r"(a[0]), "r"(a[1]), "r"(a[2]), "r"(a[3]), "r"(b[0]), "r"(b[1]));
}

// fast exp on the FMA pipe (no MUFU)
__device__ __forceinline__ float fexp(float x) {
    x = fmaxf(x, -80.0f);
    float y = x * 1.4426950408889634f;
    int   n = __float2int_rn(y);
    float f = y - (float)n;
    float p = 1.33335581e-3f;
    p = fmaf(p, f, 9.61812911e-3f);
    p = fmaf(p, f, 5.55041087e-2f);
    p = fmaf(p, f, 2.40226507e-1f);
    p = fmaf(p, f, 6.93147181e-1f);
    p = fmaf(p, f, 1.0f);
    return p * __int_as_float((n + 127) << 23);
}

extern __shared__ float dynsm[];

// ---------------------------------------------------------------------------
// fp16 GEMM — NSTG=4 x BKA=4 (32KB stages, 128KB total, 1 CTA/SM),
// 64 iterations, ONE __syncthreads per iteration (refill distance = 1 iter:
// the top-of-iteration barrier proves the previous iteration's stage is
// drained, so the post-compute fill into it needs no second barrier).
// QKV=true: emit flash-ready Q/K/V fragments. QKV=false: natural C + bias.
// ---------------------------------------------------------------------------
#define NSTG 4
#define BKA 4
#define A_STG_BYTES (8 * BKA * 512)    // 16KB
#define B_STG_BYTES (16 * BKA * 256)   // 16KB
#define STG_BYTES (A_STG_BYTES + B_STG_BYTES)   // 32KB
#define GEMM_SMEM (NSTG * STG_BYTES)            // 128KB

template<bool QKV>
__global__ __launch_bounds__(128) void gemm_mma_kernel(
    const void* __restrict__ Af, const void* __restrict__ Bf,
    const float* __restrict__ bias, float* __restrict__ C,
    int M, int N, int K)
{
    const int K16 = K >> 4;
    const int tid = threadIdx.x, lane = tid & 31, w = tid >> 5;
    const int wm = w >> 1, wn = w & 1;

    const int NT = N >> 7;
    const int per = 8 * NT;
    const int gg = blockIdx.x / per, rr = blockIdx.x % per;
    const int mtile = gg * 8 + (rr & 7);
    const int ntile = rr >> 3;

    const char* Ag = (const char*)Af + (size_t)mtile * 8 * K16 * 512;
    const char* Bg = (const char*)Bf + (size_t)ntile * 16 * K16 * 256;

    const uint32_t sb = smem_u32(dynsm);

    // ---- hoisted per-thread chunk bases (loop-invariant) ----
    const char* aBase[8];
    const char* bBase[8];
    #pragma unroll
    for (int i = 0; i < 8; i++) {
        int c = tid + i * 128;
        int mi = c >> 7, ra = c & 127;
        aBase[i] = Ag + (((size_t)mi * K16 + (ra >> 5)) * 32 + (ra & 31)) * 16;
        int ni = c >> 6, rb = c & 63;
        bBase[i] = Bg + ((size_t)ni * K16 + (rb >> 4)) * 256 + (rb & 15) * 16;
    }
    // advancing kt0 by 1 moves A source by 512 bytes, B by 256 bytes.

    auto fill = [&](int s, int kt0) {
        const uint32_t sA = sb + s * STG_BYTES;
        const uint32_t sB = sA + A_STG_BYTES;
        const size_t aAdv = (size_t)kt0 * 512;
        const size_t bAdv = (size_t)kt0 * 256;
        #pragma unroll
        for (int i = 0; i < 8; i++) CP_ASYNC16(sA + (tid + i * 128) * 16, aBase[i] + aAdv);
        #pragma unroll
        for (int i = 0; i < 8; i++) CP_ASYNC16(sB + (tid + i * 128) * 16, bBase[i] + bAdv);
        CP_COMMIT();
    };

    float acc[4][8][4];
    #pragma unroll
    for (int a = 0; a < 4; a++)
        #pragma unroll
        for (int b = 0; b < 8; b++)
            #pragma unroll
            for (int e = 0; e < 4; e++) acc[a][b][e] = 0.0f;

    const int NITER = K16 / BKA;      // 64 for K=4096
    #pragma unroll
    for (int s = 0; s < NSTG - 1; s++) fill(s, s * BKA);   // prologue: 3 stages

    char* smp = (char*)dynsm;
    int s = 0;
    for (int it = 0; it < NITER; it++) {
        char* sA = smp + s * STG_BYTES;
        char* sB = sA + A_STG_BYTES;

        // all but the 2 newest fill-groups complete => current stage ready
        asm volatile("cp.async.wait_group %0;" :: "n"(NSTG - 2));
        __syncthreads();

        #pragma unroll
        for (int ki = 0; ki < BKA; ki++) {
            uint32_t afr[4][4];
            #pragma unroll
            for (int a = 0; a < 4; a++) {
                uint4 v = *(const uint4*)(sA + (((wm * 4 + a) * BKA + ki) * 32 + lane) * 16);
                afr[a][0] = v.x; afr[a][1] = v.y; afr[a][2] = v.z; afr[a][3] = v.w;
            }
            uint32_t bfr[8][2];
            #pragma unroll
            for (int b = 0; b < 8; b++) {
                uint2 v = *(const uint2*)(sB + (((wn * 8 + b) * BKA + ki) * 32 + lane) * 8);
                bfr[b][0] = v.x; bfr[b][1] = v.y;
            }
            #pragma unroll
            for (int a = 0; a < 4; a++)
                #pragma unroll
                for (int b = 0; b < 8; b++)
                    mma_f16(acc[a][b], afr[a], bfr[b]);
        }

        // refill the stage consumed LAST iteration ((s+3)&3): the barrier at
        // the top of THIS iteration proved all warps finished reading it.
        if (it + NSTG - 1 < NITER) fill((s + NSTG - 1) & (NSTG - 1),
                                        (it + NSTG - 1) * BKA);
        else CP_COMMIT();

        s = (s + 1) & (NSTG - 1);
    }
    __syncthreads();   // all compute done before epilogue may reuse SMEM

    const int c2 = (lane & 3) * 2;

    if (QKV) {
        const int h = ntile / 3, sec = ntile % 3;
        const int cbase = ntile * 128 + wn * 64;
        if (sec == 0) {
            // ---- Q: (acc+bias)*QSCALE -> A-frags, pure register pack ----
            #pragma unroll
            for (int a = 0; a < 4; a++) {
                size_t mi = (size_t)mtile * 8 + wm * 4 + a;
                #pragma unroll
                for (int j = 0; j < 4; j++) {
                    int ka = wn * 4 + j;
                    float2 bv0 = *(const float2*)(bias + cbase + (2 * j) * 8 + c2);
                    float2 bv1 = *(const float2*)(bias + cbase + (2 * j + 1) * 8 + c2);
                    uint4 u;
                    u.x = pkh2((acc[a][2*j][0] + bv0.x) * QSCALE, (acc[a][2*j][1] + bv0.y) * QSCALE);
                    u.y = pkh2((acc[a][2*j][2] + bv0.x) * QSCALE, (acc[a][2*j][3] + bv0.y) * QSCALE);
                    u.z = pkh2((acc[a][2*j+1][0] + bv1.x) * QSCALE, (acc[a][2*j+1][1] + bv1.y) * QSCALE);
                    u.w = pkh2((acc[a][2*j+1][2] + bv1.x) * QSCALE, (acc[a][2*j+1][3] + bv1.y) * QSCALE);
                    g_qf[(((size_t)h * 256 + mi) * 8 + ka) * 32 + lane] = u;
                }
            }
        } else if (sec == 1) {
            // ---- K: acc+bias -> B-frags (n=key, k=d), pure register pack ----
            #pragma unroll
            for (int a = 0; a < 4; a++) {
                size_t na0 = (size_t)mtile * 16 + wm * 8 + a * 2;
                #pragma unroll
                for (int j = 0; j < 4; j++) {
                    int ka = wn * 4 + j;
                    float2 bv0 = *(const float2*)(bias + cbase + (2 * j) * 8 + c2);
                    float2 bv1 = *(const float2*)(bias + cbase + (2 * j + 1) * 8 + c2);
                    uint2 u0, u1;
                    u0.x = pkh2(acc[a][2*j][0] + bv0.x,   acc[a][2*j][1] + bv0.y);
                    u0.y = pkh2(acc[a][2*j+1][0] + bv1.x, acc[a][2*j+1][1] + bv1.y);
                    u1.x = pkh2(acc[a][2*j][2] + bv0.x,   acc[a][2*j][3] + bv0.y);
                    u1.y = pkh2(acc[a][2*j+1][2] + bv1.x, acc[a][2*j+1][3] + bv1.y);
                    g_kf[(((size_t)h * 512 + na0)     * 8 + ka) * 32 + lane] = u0;
                    g_kf[(((size_t)h * 512 + na0 + 1) * 8 + ka) * 32 + lane] = u1;
                }
            }
        } else {
            // ---- V: SMEM bounce transpose -> B-frags (n=d, k=key) ----
            __half* sv = (__half*)dynsm;          // [128 keys][136 d halves]
            #pragma unroll
            for (int a = 0; a < 4; a++) {
                int r = wm * 64 + a * 16 + (lane >> 2);
                #pragma unroll
                for (int b = 0; b < 8; b++) {
                    int c = wn * 64 + b * 8 + c2;
                    float2 bv = *(const float2*)(bias + ntile * 128 + c);
                    *(uint32_t*)&sv[r * 136 + c]       = pkh2(acc[a][b][0] + bv.x, acc[a][b][1] + bv.y);
                    *(uint32_t*)&sv[(r + 8) * 136 + c] = pkh2(acc[a][b][2] + bv.x, acc[a][b][3] + bv.y);
                }
            }
            __syncthreads();
            const uint16_t* sh = (const uint16_t*)dynsm;
            #pragma unroll
            for (int i = 0; i < 32; i++) {
                int blk = w + i * 4;                     // 0..127
                int t2 = blk >> 6, rem = blk & 63;
                int ka4 = rem >> 4, na = rem & 15;
                int d  = na * 8 + (lane >> 2);
                int kl = t2 * 64 + ka4 * 16 + c2;
                uint32_t x0 = sh[kl * 136 + d],       x1 = sh[(kl + 1) * 136 + d];
                uint32_t x2 = sh[(kl + 8) * 136 + d], x3 = sh[(kl + 9) * 136 + d];
                uint2 u; u.x = x0 | (x1 << 16); u.y = x2 | (x3 << 16);
                size_t g = (size_t)mtile * 2 + t2;       // = b*32 + kt
                g_vf[((((size_t)h * 64 + g) * 4 + ka4) * 16 + na) * 32 + lane] = u;
            }
        }
        return;
    }

    // ---- natural epilogue (GEMM2) ----
    const size_t row0 = (size_t)mtile * 128 + wm * 64 + (lane >> 2);
    const int col0 = ntile * 128 + wn * 64 + c2;
    #pragma unroll
    for (int a = 0; a < 4; a++) {
        #pragma unroll
        for (int b = 0; b < 8; b++) {
            int c = col0 + b * 8;
            float2 bv = *(const float2*)(bias + c);
            size_t r = row0 + a * 16;
            float2 o0; o0.x = acc[a][b][0] + bv.x; o0.y = acc[a][b][1] + bv.y;
            *(float2*)(C + r * N + c) = o0;
            float2 o1; o1.x = acc[a][b][2] + bv.x; o1.y = acc[a][b][3] + bv.y;
            *(float2*)(C + (r + 8) * N + c) = o1;
        }
    }
}

// ---------------------------------------------------------------------------
// prep: fragmentize to half (unchanged)
// ---------------------------------------------------------------------------
__global__ __launch_bounds__(128) void frag_a_kernel(
    const float* __restrict__ src, __half* __restrict__ dst, int K)
{
    __shared__ float t[32][33];
    const int k0 = blockIdx.x * 32, m0 = blockIdx.y * 32;
    const int tid = threadIdx.x;
    #pragma unroll
    for (int i = 0; i < 8; i++) {
        int idx = tid + i * 128;
        int r = idx >> 5, c = idx & 31;
        t[r][c] = src[(size_t)(m0 + r) * K + k0 + c];
    }
    __syncthreads();
    const int w = tid >> 5, lane = tid & 31;
    const int mi_l = w >> 1, ki_l = w & 1;
    const int r0 = mi_l * 16 + (lane >> 2);
    const int c0 = ki_l * 16 + (lane & 3) * 2;
    uint4 u;
    u.x = pkh2(t[r0][c0],         t[r0][c0 + 1]);
    u.y = pkh2(t[r0 + 8][c0],     t[r0 + 8][c0 + 1]);
    u.z = pkh2(t[r0][c0 + 8],     t[r0][c0 + 9]);
    u.w = pkh2(t[r0 + 8][c0 + 8], t[r0 + 8][c0 + 9]);
    ((uint4*)dst)[((size_t)((m0 >> 4) + mi_l) * (K >> 4) + (k0 >> 4) + ki_l) * 32 + lane] = u;
}

__global__ __launch_bounds__(256) void frag_b_kernel(
    const float* __restrict__ src, __half* __restrict__ dst, int K, int N)
{
    __shared__ float t[32][33];
    const int n0 = blockIdx.x * 32, k0 = blockIdx.y * 32;
    const int tid = threadIdx.x;
    #pragma unroll
    for (int i = 0; i < 4; i++) {
        int r = (tid >> 5) + i * 8;
        t[r][tid & 31] = src[(size_t)(k0 + r) * N + n0 + (tid & 31)];
    }
    __syncthreads();
    const int w = tid >> 5, lane = tid & 31;
    const int ni_l = w >> 1, ki_l = w & 1;
    const int n = ni_l * 8 + (lane >> 2);
    const int k = ki_l * 16 + (lane & 3) * 2;
    uint2 u;
    u.x = pkh2(t[k][n],     t[k + 1][n]);
    u.y = pkh2(t[k + 8][n], t[k + 9][n]);
    ((uint2*)dst)[((size_t)((n0 >> 3) + ni_l) * (K >> 4) + (k0 >> 4) + ki_l) * 32 + lane] = u;
}

// ---------------------------------------------------------------------------
// Flash attention: pre-formatted half fragments, cp.async double-buffered.
// (unchanged from round 9)
// ---------------------------------------------------------------------------
#define FL_STG 32768
#define FLASH_SMEM_B (2 * FL_STG + 768)

__global__ __launch_bounds__(128) void flash_mma_kernel(
    const float* __restrict__ alibi, const int* __restrict__ amask,
    __half* __restrict__ attn_out)
{
    const int qt = blockIdx.x, h = blockIdx.y, bb = blockIdx.z;
    const int qb = qt * 64;
    const int tid = threadIdx.x, lane = tid & 31, w = tid >> 5;
    const int c2 = (lane & 3) * 2;

    const uint32_t sb = smem_u32(dynsm);
    float* sAl = (float*)((char*)dynsm + 2 * FL_STG);

    const float* alib = alibi + ((size_t)bb * NHh + h) * Ss;
    const int* amk = amask + (size_t)bb * Ss;

    auto fill = [&](int s, int kt) {
        const char* Ks = (const char*)(g_kf + (((size_t)h * 512 + bb * 256 + (size_t)kt * 8) * 8) * 32);
        const char* Vs = (const char*)(g_vf + ((((size_t)h * 64 + bb * 32 + kt) * 4) * 16) * 32);
        uint32_t sK = sb + s * FL_STG;
        uint32_t sV = sK + 16384;
        #pragma unroll
        for (int i = 0; i < 8; i++) {
            int c = (tid + i * 128) * 16;
            CP_ASYNC16(sK + c, Ks + c);
            CP_ASYNC16(sV + c, Vs + c);
        }
        CP_COMMIT();
    };

    fill(0, 0);

    uint32_t qf[8][4];
    {
        size_t mi = (size_t)bb * 128 + qt * 4 + w;
        const uint4* qsrc = g_qf + ((size_t)h * 256 + mi) * 8 * 32 + lane;
        #pragma unroll
        for (int ka = 0; ka < 8; ka++) {
            uint4 v = qsrc[ka * 32];
            qf[ka][0] = v.x; qf[ka][1] = v.y; qf[ka][2] = v.z; qf[ka][3] = v.w;
        }
    }

    float m0 = -1e29f, m1 = -1e29f, l0 = 0.0f, l1 = 0.0f;
    float acc[16][4];
    #pragma unroll
    for (int na = 0; na < 16; na++)
        #pragma unroll
        for (int e = 0; e < 4; e++) acc[na][e] = 0.0f;

    const int qg0 = qb + w * 16 + (lane >> 2);
    const int qg1 = qg0 + 8;

    for (int kt = 0; kt <= qt; kt++) {
        const int cur = kt & 1;
        const int kb = kt * 64;

        if (kt < qt) fill(cur ^ 1, kt + 1);
        else CP_COMMIT();

        asm volatile("cp.async.wait_group %0;" :: "n"(1));
        if (tid < 64) {
            int kg = kb + tid;
            sAl[cur * 96 + tid] = (amk[kg] > 0) ? alib[kg] : -1e30f;
        }
        __syncthreads();

        const uint2* Kf2 = (const uint2*)((char*)dynsm + cur * FL_STG);
        const uint2* Vf2 = (const uint2*)((char*)dynsm + cur * FL_STG + 16384);
        const float* sAc = sAl + cur * 96;

        float sfr[8][4];
        #pragma unroll
        for (int na = 0; na < 8; na++)
            #pragma unroll
            for (int e = 0; e < 4; e++) sfr[na][e] = 0.0f;

        #pragma unroll
        for (int ka = 0; ka < 8; ka++) {
            #pragma unroll
            for (int na = 0; na < 8; na++) {
                uint2 bv = Kf2[(na * 8 + ka) * 32 + lane];
                uint32_t br[2] = {bv.x, bv.y};
                mma_f16(sfr[na], qf[ka], br);
            }
        }

        const bool diag = (kt == qt);
        float tm0 = -1e30f, tm1 = -1e30f;
        #pragma unroll
        for (int na = 0; na < 8; na++) {
            int c0 = na * 8 + c2;
            int kg0 = kb + c0;
            float al0 = sAc[c0], al1 = sAc[c0 + 1];
            if (diag) {
                sfr[na][0] = (kg0     <= qg0) ? sfr[na][0] + al0 : -1e30f;
                sfr[na][1] = (kg0 + 1 <= qg0) ? sfr[na][1] + al1 : -1e30f;
                sfr[na][2] = (kg0     <= qg1) ? sfr[na][2] + al0 : -1e30f;
                sfr[na][3] = (kg0 + 1 <= qg1) ? sfr[na][3] + al1 : -1e30f;
            } else {
                sfr[na][0] += al0; sfr[na][1] += al1;
                sfr[na][2] += al0; sfr[na][3] += al1;
            }
            tm0 = fmaxf(tm0, fmaxf(sfr[na][0], sfr[na][1]));
            tm1 = fmaxf(tm1, fmaxf(sfr[na][2], sfr[na][3]));
        }
        tm0 = fmaxf(tm0, __shfl_xor_sync(0xffffffffu, tm0, 1));
        tm0 = fmaxf(tm0, __shfl_xor_sync(0xffffffffu, tm0, 2));
        tm1 = fmaxf(tm1, __shfl_xor_sync(0xffffffffu, tm1, 1));
        tm1 = fmaxf(tm1, __shfl_xor_sync(0xffffffffu, tm1, 2));

        float mn0 = fmaxf(m0, tm0), mn1 = fmaxf(m1, tm1);
        float corr0 = fexp(m0 - mn0), corr1 = fexp(m1 - mn1);

        float rs0 = 0.0f, rs1 = 0.0f;
        #pragma unroll
        for (int na = 0; na < 8; na++) {
            sfr[na][0] = fexp(sfr[na][0] - mn0);
            sfr[na][1] = fexp(sfr[na][1] - mn0);
            sfr[na][2] = fexp(sfr[na][2] - mn1);
            sfr[na][3] = fexp(sfr[na][3] - mn1);
            rs0 += sfr[na][0] + sfr[na][1];
            rs1 += sfr[na][2] + sfr[na][3];
        }
        rs0 += __shfl_xor_sync(0xffffffffu, rs0, 1);
        rs0 += __shfl_xor_sync(0xffffffffu, rs0, 2);
        rs1 += __shfl_xor_sync(0xffffffffu, rs1, 1);
        rs1 += __shfl_xor_sync(0xffffffffu, rs1, 2);
        l0 = l0 * corr0 + rs0;  m0 = mn0;
        l1 = l1 * corr1 + rs1;  m1 = mn1;
        #pragma unroll
        for (int na = 0; na < 16; na++) {
            acc[na][0] *= corr0; acc[na][1] *= corr0;
            acc[na][2] *= corr1; acc[na][3] *= corr1;
        }

        uint32_t pa[4][4];
        #pragma unroll
        for (int j = 0; j < 4; j++) {
            pa[j][0] = pkh2(sfr[2 * j][0],     sfr[2 * j][1]);
            pa[j][1] = pkh2(sfr[2 * j][2],     sfr[2 * j][3]);
            pa[j][2] = pkh2(sfr[2 * j + 1][0], sfr[2 * j + 1][1]);
            pa[j][3] = pkh2(sfr[2 * j + 1][2], sfr[2 * j + 1][3]);
        }

        #pragma unroll
        for (int ka4 = 0; ka4 < 4; ka4++) {
            #pragma unroll
            for (int na = 0; na < 16; na++) {
                uint2 bv = Vf2[(ka4 * 16 + na) * 32 + lane];
                uint32_t br[2] = {bv.x, bv.y};
                mma_f16(acc[na], pa[ka4], br);
            }
        }
        __syncthreads();
    }

    {
        float inv0 = 1.0f / fmaxf(l0, 1e-30f);
        float inv1 = 1.0f / fmaxf(l1, 1e-30f);
        size_t mi = (size_t)(bb * Ss + qb + w * 16) >> 4;
        uint4* ao = (uint4*)attn_out;
        #pragma unroll
        for (int j = 0; j < 8; j++) {
            uint4 u;
            u.x = pkh2(acc[2 * j][0] * inv0,     acc[2 * j][1] * inv0);
            u.y = pkh2(acc[2 * j][2] * inv1,     acc[2 * j][3] * inv1);
            u.z = pkh2(acc[2 * j + 1][0] * inv0, acc[2 * j + 1][1] * inv0);
            u.w = pkh2(acc[2 * j + 1][2] * inv1, acc[2 * j + 1][3] * inv1);
            ao[(mi * 256 + (size_t)h * 8 + j) * 32 + lane] = u;
        }
    }
}

// ---------------------------------------------------------------------------
extern "C" void kernel_launch(void* const* d_in, const int* in_sizes, int n_in,
                              void* d_out, int out_size)
{
    const float* hidden = (const float*)d_in[0];
    const float* alibi  = (const float*)d_in[1];
    const float* w_qkv  = (const float*)d_in[2];
    const float* b_qkv  = (const float*)d_in[3];
    const float* w_out  = (const float*)d_in[4];
    const float* b_out  = (const float*)d_in[5];
    const int*   amask  = (const int*)d_in[6];
    float* out = (float*)d_out;

    __half *attn, *hid, *w1t, *w2t;
    cudaGetSymbolAddress((void**)&attn, g_attn);
    cudaGetSymbolAddress((void**)&hid,  g_hid);
    cudaGetSymbolAddress((void**)&w1t,  g_w1t);
    cudaGetSymbolAddress((void**)&w2t,  g_w2t);

    cudaFuncSetAttribute(gemm_mma_kernel<true>,
                         cudaFuncAttributeMaxDynamicSharedMemorySize, GEMM_SMEM);
    cudaFuncSetAttribute(gemm_mma_kernel<false>,
                         cudaFuncAttributeMaxDynamicSharedMemorySize, GEMM_SMEM);
    cudaFuncSetAttribute(flash_mma_kernel,
                         cudaFuncAttributeMaxDynamicSharedMemorySize, FLASH_SMEM_B);

    // prep: fragmentize to half
    frag_a_kernel<<<dim3(Hh / 32, Mm / 32), 128>>>(hidden, hid, Hh);
    frag_b_kernel<<<dim3(QKVN / 32, Hh / 32), 256>>>(w_qkv, w1t, Hh, QKVN);
    frag_b_kernel<<<dim3(Hh / 32, Hh / 32), 256>>>(w_out, w2t, Hh, Hh);

    // 1) QKV projection -> flash-ready Q/K/V fragment buffers
    gemm_mma_kernel<true><<<(Mm / 128) * (QKVN / 128), 128, GEMM_SMEM>>>(
        hid, w1t, b_qkv, nullptr, Mm, QKVN, Hh);

    // 2) flash attention (pure cp.async + fp16 mma)
    flash_mma_kernel<<<dim3(Ss / 64, NHh, Bb), 128, FLASH_SMEM_B>>>(
        alibi, amask, attn);

    // 3) output projection
    gemm_mma_kernel<false><<<(Mm / 128) * (Hh / 128), 128, GEMM_SMEM>>>(
        attn, w2t, b_out, out, Mm, Hh, Hh);
}

// round 16
// speedup vs baseline: 1.1323x; 1.1323x over previous
#include <cuda_runtime.h>
#include <cuda_fp16.h>
#include <cuda_bf16.h>
#include <cstdint>
#include <cstddef>

// ---------------- problem constants ----------------
#define Bb   2
#define Ss   2048
#define Hh   4096
#define NHh  32
#define HDd  128
#define QKVN 12288            // NH * 3 * HD
#define Mm   4096             // B * S

#define QSCALE 0.08838834764831845f

// ---------------- scratch (__device__ globals; no allocs allowed) ----------
__device__ __half g_attn[(size_t)Mm * Hh];     // flash out, A-frag half
__device__ __half g_hid [(size_t)Mm * Hh];     // hidden, A-frag half
__device__ __half g_w1t [(size_t)QKVN * Hh];   // w_qkv, B-frag half
__device__ __half g_w2t [(size_t)Hh * Hh];     // w_out, B-frag half
// flash-ready fragment buffers written by GEMM1:
__device__ uint4 g_qf[(size_t)NHh * 256 * 8 * 32];
__device__ uint2 g_kf[(size_t)NHh * 512 * 8 * 32];
__device__ uint2 g_vf[(size_t)NHh * 64 * 4 * 16 * 32];

// ---------------- helpers ----------------
__device__ __forceinline__ uint32_t smem_u32(const void* p) {
    uint32_t a;
    asm("{ .reg .u64 t; cvta.to.shared.u64 t, %1; cvt.u32.u64 %0, t; }" : "=r"(a) : "l"(p));
    return a;
}
__device__ __forceinline__ uint32_t pkh2(float a, float b) {
    __half2 h = __floats2half2_rn(a, b);
    return *(uint32_t*)&h;
}
#define CP_ASYNC16(dst, src) \
    asm volatile("cp.async.cg.shared.global [%0], [%1], 16;" :: "r"(dst), "l"(src))
#define CP_COMMIT() asm volatile("cp.async.commit_group;")

__device__ __forceinline__ void mma_f16(float* d, const uint32_t* a, const uint32_t* b) {
    asm volatile(
        "mma.sync.aligned.m16n8k16.row.col.f32.f16.f16.f32 "
        "{%0,%1,%2,%3}, {%4,%5,%6,%7}, {%8,%9}, {%0,%1,%2,%3};"
        : "+f"(d[0]), "+f"(d[1]), "+f"(d[2]), "+f"(d[3])
        : "r"(a[0]), "r"(a[1]), "r"(a[2]), "r"(a[3]), "r"(b[0]), "r"(b[1]));
}

// fast exp on the FMA pipe (no MUFU)
__device__ __forceinline__ float fexp(float x) {
    x = fmaxf(x, -80.0f);
    float y = x * 1.4426950408889634f;
    int   n = __float2int_rn(y);
    float f = y - (float)n;
    float p = 1.33335581e-3f;
    p = fmaf(p, f, 9.61812911e-3f);
    p = fmaf(p, f, 5.55041087e-2f);
    p = fmaf(p, f, 2.40226507e-1f);
    p = fmaf(p, f, 6.93147181e-1f);
    p = fmaf(p, f, 1.0f);
    return p * __int_as_float((n + 127) << 23);
}

extern __shared__ float dynsm[];

// ---------------------------------------------------------------------------
// fp16 GEMM — round-13 pipeline (NSTG=3, BKA=4, 64 iters, runtime stage idx,
// hoisted gmem addressing). Proven local optimum: tensor=74.6%, 2 CTAs/SM.
// QKV=true: emit flash-ready Q/K/V fragments. QKV=false: natural C + bias.
// ---------------------------------------------------------------------------
#define NSTG 3
#define BKA 4
#define A_STG_BYTES (8 * BKA * 512)    // 16KB
#define B_STG_BYTES (16 * BKA * 256)   // 16KB
#define STG_BYTES (A_STG_BYTES + B_STG_BYTES)
#define GEMM_SMEM (NSTG * STG_BYTES)

template<bool QKV>
__global__ __launch_bounds__(128) void gemm_mma_kernel(
    const void* __restrict__ Af, const void* __restrict__ Bf,
    const float* __restrict__ bias, float* __restrict__ C,
    int M, int N, int K)
{
    const int K16 = K >> 4;
    const int tid = threadIdx.x, lane = tid & 31, w = tid >> 5;
    const int wm = w >> 1, wn = w & 1;

    const int NT = N >> 7;
    const int per = 8 * NT;
    const int gg = blockIdx.x / per, rr = blockIdx.x % per;
    const int mtile = gg * 8 + (rr & 7);
    const int ntile = rr >> 3;

    const char* Ag = (const char*)Af + (size_t)mtile * 8 * K16 * 512;
    const char* Bg = (const char*)Bf + (size_t)ntile * 16 * K16 * 256;

    const uint32_t sb = smem_u32(dynsm);

    // ---- hoisted per-thread chunk bases (loop-invariant) ----
    const char* aBase[8];
    const char* bBase[8];
    #pragma unroll
    for (int i = 0; i < 8; i++) {
        int c = tid + i * 128;
        int mi = c >> 7, ra = c & 127;
        aBase[i] = Ag + (((size_t)mi * K16 + (ra >> 5)) * 32 + (ra & 31)) * 16;
        int ni = c >> 6, rb = c & 63;
        bBase[i] = Bg + ((size_t)ni * K16 + (rb >> 4)) * 256 + (rb & 15) * 16;
    }
    // advancing kt0 by 1 moves A source by 512 bytes, B by 256 bytes.

    auto fill = [&](int s, int kt0) {
        const uint32_t sA = sb + s * STG_BYTES;
        const uint32_t sB = sA + A_STG_BYTES;
        const size_t aAdv = (size_t)kt0 * 512;
        const size_t bAdv = (size_t)kt0 * 256;
        #pragma unroll
        for (int i = 0; i < 8; i++) CP_ASYNC16(sA + (tid + i * 128) * 16, aBase[i] + aAdv);
        #pragma unroll
        for (int i = 0; i < 8; i++) CP_ASYNC16(sB + (tid + i * 128) * 16, bBase[i] + bAdv);
        CP_COMMIT();
    };

    float acc[4][8][4];
    #pragma unroll
    for (int a = 0; a < 4; a++)
        #pragma unroll
        for (int b = 0; b < 8; b++)
            #pragma unroll
            for (int e = 0; e < 4; e++) acc[a][b][e] = 0.0f;

    const int NITER = K16 / BKA;      // 64 for K=4096
    #pragma unroll
    for (int s = 0; s < NSTG; s++) fill(s, s * BKA);

    char* smp = (char*)dynsm;
    int s = 0;
    for (int it = 0; it < NITER; it++) {
        char* sA = smp + s * STG_BYTES;
        char* sB = sA + A_STG_BYTES;

        asm volatile("cp.async.wait_group %0;" :: "n"(NSTG - 1));
        __syncthreads();

        #pragma unroll
        for (int ki = 0; ki < BKA; ki++) {
            uint32_t afr[4][4];
            #pragma unroll
            for (int a = 0; a < 4; a++) {
                uint4 v = *(const uint4*)(sA + (((wm * 4 + a) * BKA + ki) * 32 + lane) * 16);
                afr[a][0] = v.x; afr[a][1] = v.y; afr[a][2] = v.z; afr[a][3] = v.w;
            }
            uint32_t bfr[8][2];
            #pragma unroll
            for (int b = 0; b < 8; b++) {
                uint2 v = *(const uint2*)(sB + (((wn * 8 + b) * BKA + ki) * 32 + lane) * 8);
                bfr[b][0] = v.x; bfr[b][1] = v.y;
            }
            #pragma unroll
            for (int a = 0; a < 4; a++)
                #pragma unroll
                for (int b = 0; b < 8; b++)
                    mma_f16(acc[a][b], afr[a], bfr[b]);
        }
        __syncthreads();

        if (it + NSTG < NITER) fill(s, (it + NSTG) * BKA);
        else CP_COMMIT();

        s = (s == NSTG - 1) ? 0 : s + 1;
    }

    const int c2 = (lane & 3) * 2;

    if (QKV) {
        const int h = ntile / 3, sec = ntile % 3;
        const int cbase = ntile * 128 + wn * 64;
        if (sec == 0) {
            // ---- Q: (acc+bias)*QSCALE -> A-frags, pure register pack ----
            #pragma unroll
            for (int a = 0; a < 4; a++) {
                size_t mi = (size_t)mtile * 8 + wm * 4 + a;
                #pragma unroll
                for (int j = 0; j < 4; j++) {
                    int ka = wn * 4 + j;
                    float2 bv0 = *(const float2*)(bias + cbase + (2 * j) * 8 + c2);
                    float2 bv1 = *(const float2*)(bias + cbase + (2 * j + 1) * 8 + c2);
                    uint4 u;
                    u.x = pkh2((acc[a][2*j][0] + bv0.x) * QSCALE, (acc[a][2*j][1] + bv0.y) * QSCALE);
                    u.y = pkh2((acc[a][2*j][2] + bv0.x) * QSCALE, (acc[a][2*j][3] + bv0.y) * QSCALE);
                    u.z = pkh2((acc[a][2*j+1][0] + bv1.x) * QSCALE, (acc[a][2*j+1][1] + bv1.y) * QSCALE);
                    u.w = pkh2((acc[a][2*j+1][2] + bv1.x) * QSCALE, (acc[a][2*j+1][3] + bv1.y) * QSCALE);
                    g_qf[(((size_t)h * 256 + mi) * 8 + ka) * 32 + lane] = u;
                }
            }
        } else if (sec == 1) {
            // ---- K: acc+bias -> B-frags (n=key, k=d), pure register pack ----
            #pragma unroll
            for (int a = 0; a < 4; a++) {
                size_t na0 = (size_t)mtile * 16 + wm * 8 + a * 2;
                #pragma unroll
                for (int j = 0; j < 4; j++) {
                    int ka = wn * 4 + j;
                    float2 bv0 = *(const float2*)(bias + cbase + (2 * j) * 8 + c2);
                    float2 bv1 = *(const float2*)(bias + cbase + (2 * j + 1) * 8 + c2);
                    uint2 u0, u1;
                    u0.x = pkh2(acc[a][2*j][0] + bv0.x,   acc[a][2*j][1] + bv0.y);
                    u0.y = pkh2(acc[a][2*j+1][0] + bv1.x, acc[a][2*j+1][1] + bv1.y);
                    u1.x = pkh2(acc[a][2*j][2] + bv0.x,   acc[a][2*j][3] + bv0.y);
                    u1.y = pkh2(acc[a][2*j+1][2] + bv1.x, acc[a][2*j+1][3] + bv1.y);
                    g_kf[(((size_t)h * 512 + na0)     * 8 + ka) * 32 + lane] = u0;
                    g_kf[(((size_t)h * 512 + na0 + 1) * 8 + ka) * 32 + lane] = u1;
                }
            }
        } else {
            // ---- V: SMEM bounce transpose -> B-frags (n=d, k=key) ----
            __half* sv = (__half*)dynsm;          // [128 keys][136 d halves]
            #pragma unroll
            for (int a = 0; a < 4; a++) {
                int r = wm * 64 + a * 16 + (lane >> 2);
                #pragma unroll
                for (int b = 0; b < 8; b++) {
                    int c = wn * 64 + b * 8 + c2;
                    float2 bv = *(const float2*)(bias + ntile * 128 + c);
                    *(uint32_t*)&sv[r * 136 + c]       = pkh2(acc[a][b][0] + bv.x, acc[a][b][1] + bv.y);
                    *(uint32_t*)&sv[(r + 8) * 136 + c] = pkh2(acc[a][b][2] + bv.x, acc[a][b][3] + bv.y);
                }
            }
            __syncthreads();
            const uint16_t* sh = (const uint16_t*)dynsm;
            #pragma unroll
            for (int i = 0; i < 32; i++) {
                int blk = w + i * 4;                     // 0..127
                int t2 = blk >> 6, rem = blk & 63;
                int ka4 = rem >> 4, na = rem & 15;
                int d  = na * 8 + (lane >> 2);
                int kl = t2 * 64 + ka4 * 16 + c2;
                uint32_t x0 = sh[kl * 136 + d],       x1 = sh[(kl + 1) * 136 + d];
                uint32_t x2 = sh[(kl + 8) * 136 + d], x3 = sh[(kl + 9) * 136 + d];
                uint2 u; u.x = x0 | (x1 << 16); u.y = x2 | (x3 << 16);
                size_t g = (size_t)mtile * 2 + t2;       // = b*32 + kt
                g_vf[((((size_t)h * 64 + g) * 4 + ka4) * 16 + na) * 32 + lane] = u;
            }
        }
        return;
    }

    // ---- natural epilogue (GEMM2) ----
    const size_t row0 = (size_t)mtile * 128 + wm * 64 + (lane >> 2);
    const int col0 = ntile * 128 + wn * 64 + c2;
    #pragma unroll
    for (int a = 0; a < 4; a++) {
        #pragma unroll
        for (int b = 0; b < 8; b++) {
            int c = col0 + b * 8;
            float2 bv = *(const float2*)(bias + c);
            size_t r = row0 + a * 16;
            float2 o0; o0.x = acc[a][b][0] + bv.x; o0.y = acc[a][b][1] + bv.y;
            *(float2*)(C + r * N + c) = o0;
            float2 o1; o1.x = acc[a][b][2] + bv.x; o1.y = acc[a][b][3] + bv.y;
            *(float2*)(C + (r + 8) * N + c) = o1;
        }
    }
}

// ---------------------------------------------------------------------------
// prep: fragmentize to half (unchanged)
// ---------------------------------------------------------------------------
__global__ __launch_bounds__(128) void frag_a_kernel(
    const float* __restrict__ src, __half* __restrict__ dst, int K)
{
    __shared__ float t[32][33];
    const int k0 = blockIdx.x * 32, m0 = blockIdx.y * 32;
    const int tid = threadIdx.x;
    #pragma unroll
    for (int i = 0; i < 8; i++) {
        int idx = tid + i * 128;
        int r = idx >> 5, c = idx & 31;
        t[r][c] = src[(size_t)(m0 + r) * K + k0 + c];
    }
    __syncthreads();
    const int w = tid >> 5, lane = tid & 31;
    const int mi_l = w >> 1, ki_l = w & 1;
    const int r0 = mi_l * 16 + (lane >> 2);
    const int c0 = ki_l * 16 + (lane & 3) * 2;
    uint4 u;
    u.x = pkh2(t[r0][c0],         t[r0][c0 + 1]);
    u.y = pkh2(t[r0 + 8][c0],     t[r0 + 8][c0 + 1]);
    u.z = pkh2(t[r0][c0 + 8],     t[r0][c0 + 9]);
    u.w = pkh2(t[r0 + 8][c0 + 8], t[r0 + 8][c0 + 9]);
    ((uint4*)dst)[((size_t)((m0 >> 4) + mi_l) * (K >> 4) + (k0 >> 4) + ki_l) * 32 + lane] = u;
}

__global__ __launch_bounds__(256) void frag_b_kernel(
    const float* __restrict__ src, __half* __restrict__ dst, int K, int N)
{
    __shared__ float t[32][33];
    const int n0 = blockIdx.x * 32, k0 = blockIdx.y * 32;
    const int tid = threadIdx.x;
    #pragma unroll
    for (int i = 0; i < 4; i++) {
        int r = (tid >> 5) + i * 8;
        t[r][tid & 31] = src[(size_t)(k0 + r) * N + n0 + (tid & 31)];
    }
    __syncthreads();
    const int w = tid >> 5, lane = tid & 31;
    const int ni_l = w >> 1, ki_l = w & 1;
    const int n = ni_l * 8 + (lane >> 2);
    const int k = ki_l * 16 + (lane & 3) * 2;
    uint2 u;
    u.x = pkh2(t[k][n],     t[k + 1][n]);
    u.y = pkh2(t[k + 8][n], t[k + 9][n]);
    ((uint2*)dst)[((size_t)((n0 >> 3) + ni_l) * (K >> 4) + (k0 >> 4) + ki_l) * 32 + lane] = u;
}

// ---------------------------------------------------------------------------
// Flash attention: pre-formatted half fragments, cp.async double-buffered.
// LPT scheduling: qt REVERSED vs blockIdx so heaviest CTAs launch first.
// ---------------------------------------------------------------------------
#define FL_STG 32768
#define FLASH_SMEM_B (2 * FL_STG + 768)

__global__ __launch_bounds__(128) void flash_mma_kernel(
    const float* __restrict__ alibi, const int* __restrict__ amask,
    __half* __restrict__ attn_out)
{
    const int qt = gridDim.x - 1 - blockIdx.x;   // longest-job-first
    const int h = blockIdx.y, bb = blockIdx.z;
    const int qb = qt * 64;
    const int tid = threadIdx.x, lane = tid & 31, w = tid >> 5;
    const int c2 = (lane & 3) * 2;

    const uint32_t sb = smem_u32(dynsm);
    float* sAl = (float*)((char*)dynsm + 2 * FL_STG);

    const float* alib = alibi + ((size_t)bb * NHh + h) * Ss;
    const int* amk = amask + (size_t)bb * Ss;

    auto fill = [&](int s, int kt) {
        const char* Ks = (const char*)(g_kf + (((size_t)h * 512 + bb * 256 + (size_t)kt * 8) * 8) * 32);
        const char* Vs = (const char*)(g_vf + ((((size_t)h * 64 + bb * 32 + kt) * 4) * 16) * 32);
        uint32_t sK = sb + s * FL_STG;
        uint32_t sV = sK + 16384;
        #pragma unroll
        for (int i = 0; i < 8; i++) {
            int c = (tid + i * 128) * 16;
            CP_ASYNC16(sK + c, Ks + c);
            CP_ASYNC16(sV + c, Vs + c);
        }
        CP_COMMIT();
    };

    fill(0, 0);

    uint32_t qf[8][4];
    {
        size_t mi = (size_t)bb * 128 + qt * 4 + w;
        const uint4* qsrc = g_qf + ((size_t)h * 256 + mi) * 8 * 32 + lane;
        #pragma unroll
        for (int ka = 0; ka < 8; ka++) {
            uint4 v = qsrc[ka * 32];
            qf[ka][0] = v.x; qf[ka][1] = v.y; qf[ka][2] = v.z; qf[ka][3] = v.w;
        }
    }

    float m0 = -1e29f, m1 = -1e29f, l0 = 0.0f, l1 = 0.0f;
    float acc[16][4];
    #pragma unroll
    for (int na = 0; na < 16; na++)
        #pragma unroll
        for (int e = 0; e < 4; e++) acc[na][e] = 0.0f;

    const int qg0 = qb + w * 16 + (lane >> 2);
    const int qg1 = qg0 + 8;

    for (int kt = 0; kt <= qt; kt++) {
        const int cur = kt & 1;
        const int kb = kt * 64;

        if (kt < qt) fill(cur ^ 1, kt + 1);
        else CP_COMMIT();

        asm volatile("cp.async.wait_group %0;" :: "n"(1));
        if (tid < 64) {
            int kg = kb + tid;
            sAl[cur * 96 + tid] = (amk[kg] > 0) ? alib[kg] : -1e30f;
        }
        __syncthreads();

        const uint2* Kf2 = (const uint2*)((char*)dynsm + cur * FL_STG);
        const uint2* Vf2 = (const uint2*)((char*)dynsm + cur * FL_STG + 16384);
        const float* sAc = sAl + cur * 96;

        float sfr[8][4];
        #pragma unroll
        for (int na = 0; na < 8; na++)
            #pragma unroll
            for (int e = 0; e < 4; e++) sfr[na][e] = 0.0f;

        #pragma unroll
        for (int ka = 0; ka < 8; ka++) {
            #pragma unroll
            for (int na = 0; na < 8; na++) {
                uint2 bv = Kf2[(na * 8 + ka) * 32 + lane];
                uint32_t br[2] = {bv.x, bv.y};
                mma_f16(sfr[na], qf[ka], br);
            }
        }

        const bool diag = (kt == qt);
        float tm0 = -1e30f, tm1 = -1e30f;
        #pragma unroll
        for (int na = 0; na < 8; na++) {
            int c0 = na * 8 + c2;
            int kg0 = kb + c0;
            float al0 = sAc[c0], al1 = sAc[c0 + 1];
            if (diag) {
                sfr[na][0] = (kg0     <= qg0) ? sfr[na][0] + al0 : -1e30f;
                sfr[na][1] = (kg0 + 1 <= qg0) ? sfr[na][1] + al1 : -1e30f;
                sfr[na][2] = (kg0     <= qg1) ? sfr[na][2] + al0 : -1e30f;
                sfr[na][3] = (kg0 + 1 <= qg1) ? sfr[na][3] + al1 : -1e30f;
            } else {
                sfr[na][0] += al0; sfr[na][1] += al1;
                sfr[na][2] += al0; sfr[na][3] += al1;
            }
            tm0 = fmaxf(tm0, fmaxf(sfr[na][0], sfr[na][1]));
            tm1 = fmaxf(tm1, fmaxf(sfr[na][2], sfr[na][3]));
        }
        tm0 = fmaxf(tm0, __shfl_xor_sync(0xffffffffu, tm0, 1));
        tm0 = fmaxf(tm0, __shfl_xor_sync(0xffffffffu, tm0, 2));
        tm1 = fmaxf(tm1, __shfl_xor_sync(0xffffffffu, tm1, 1));
        tm1 = fmaxf(tm1, __shfl_xor_sync(0xffffffffu, tm1, 2));

        float mn0 = fmaxf(m0, tm0), mn1 = fmaxf(m1, tm1);
        float corr0 = fexp(m0 - mn0), corr1 = fexp(m1 - mn1);

        float rs0 = 0.0f, rs1 = 0.0f;
        #pragma unroll
        for (int na = 0; na < 8; na++) {
            sfr[na][0] = fexp(sfr[na][0] - mn0);
            sfr[na][1] = fexp(sfr[na][1] - mn0);
            sfr[na][2] = fexp(sfr[na][2] - mn1);
            sfr[na][3] = fexp(sfr[na][3] - mn1);
            rs0 += sfr[na][0] + sfr[na][1];
            rs1 += sfr[na][2] + sfr[na][3];
        }
        rs0 += __shfl_xor_sync(0xffffffffu, rs0, 1);
        rs0 += __shfl_xor_sync(0xffffffffu, rs0, 2);
        rs1 += __shfl_xor_sync(0xffffffffu, rs1, 1);
        rs1 += __shfl_xor_sync(0xffffffffu, rs1, 2);
        l0 = l0 * corr0 + rs0;  m0 = mn0;
        l1 = l1 * corr1 + rs1;  m1 = mn1;
        #pragma unroll
        for (int na = 0; na < 16; na++) {
            acc[na][0] *= corr0; acc[na][1] *= corr0;
            acc[na][2] *= corr1; acc[na][3] *= corr1;
        }

        uint32_t pa[4][4];
        #pragma unroll
        for (int j = 0; j < 4; j++) {
            pa[j][0] = pkh2(sfr[2 * j][0],     sfr[2 * j][1]);
            pa[j][1] = pkh2(sfr[2 * j][2],     sfr[2 * j][3]);
            pa[j][2] = pkh2(sfr[2 * j + 1][0], sfr[2 * j + 1][1]);
            pa[j][3] = pkh2(sfr[2 * j + 1][2], sfr[2 * j + 1][3]);
        }

        #pragma unroll
        for (int ka4 = 0; ka4 < 4; ka4++) {
            #pragma unroll
            for (int na = 0; na < 16; na++) {
                uint2 bv = Vf2[(ka4 * 16 + na) * 32 + lane];
                uint32_t br[2] = {bv.x, bv.y};
                mma_f16(acc[na], pa[ka4], br);
            }
        }
        __syncthreads();
    }

    {
        float inv0 = 1.0f / fmaxf(l0, 1e-30f);
        float inv1 = 1.0f / fmaxf(l1, 1e-30f);
        size_t mi = (size_t)(bb * Ss + qb + w * 16) >> 4;
        uint4* ao = (uint4*)attn_out;
        #pragma unroll
        for (int j = 0; j < 8; j++) {
            uint4 u;
            u.x = pkh2(acc[2 * j][0] * inv0,     acc[2 * j][1] * inv0);
            u.y = pkh2(acc[2 * j][2] * inv1,     acc[2 * j][3] * inv1);
            u.z = pkh2(acc[2 * j + 1][0] * inv0, acc[2 * j + 1][1] * inv0);
            u.w = pkh2(acc[2 * j + 1][2] * inv1, acc[2 * j + 1][3] * inv1);
            ao[(mi * 256 + (size_t)h * 8 + j) * 32 + lane] = u;
        }
    }
}

// ---------------------------------------------------------------------------
extern "C" void kernel_launch(void* const* d_in, const int* in_sizes, int n_in,
                              void* d_out, int out_size)
{
    const float* hidden = (const float*)d_in[0];
    const float* alibi  = (const float*)d_in[1];
    const float* w_qkv  = (const float*)d_in[2];
    const float* b_qkv  = (const float*)d_in[3];
    const float* w_out  = (const float*)d_in[4];
    const float* b_out  = (const float*)d_in[5];
    const int*   amask  = (const int*)d_in[6];
    float* out = (float*)d_out;

    __half *attn, *hid, *w1t, *w2t;
    cudaGetSymbolAddress((void**)&attn, g_attn);
    cudaGetSymbolAddress((void**)&hid,  g_hid);
    cudaGetSymbolAddress((void**)&w1t,  g_w1t);
    cudaGetSymbolAddress((void**)&w2t,  g_w2t);

    cudaFuncSetAttribute(gemm_mma_kernel<true>,
                         cudaFuncAttributeMaxDynamicSharedMemorySize, GEMM_SMEM);
    cudaFuncSetAttribute(gemm_mma_kernel<false>,
                         cudaFuncAttributeMaxDynamicSharedMemorySize, GEMM_SMEM);
    cudaFuncSetAttribute(flash_mma_kernel,
                         cudaFuncAttributeMaxDynamicSharedMemorySize, FLASH_SMEM_B);

    // prep: fragmentize to half
    frag_a_kernel<<<dim3(Hh / 32, Mm / 32), 128>>>(hidden, hid, Hh);
    frag_b_kernel<<<dim3(QKVN / 32, Hh / 32), 256>>>(w_qkv, w1t, Hh, QKVN);
    frag_b_kernel<<<dim3(Hh / 32, Hh / 32), 256>>>(w_out, w2t, Hh, Hh);

    // 1) QKV projection -> flash-ready Q/K/V fragment buffers
    gemm_mma_kernel<true><<<(Mm / 128) * (QKVN / 128), 128, GEMM_SMEM>>>(
        hid, w1t, b_qkv, nullptr, Mm, QKVN, Hh);

    // 2) flash attention (pure cp.async + fp16 mma, LPT-ordered)
    flash_mma_kernel<<<dim3(Ss / 64, NHh, Bb), 128, FLASH_SMEM_B>>>(
        alibi, amask, attn);

    // 3) output projection
    gemm_mma_kernel<false><<<(Mm / 128) * (Hh / 128), 128, GEMM_SMEM>>>(
        attn, w2t, b_out, out, Mm, Hh, Hh);
}

// round 17
// speedup vs baseline: 1.1368x; 1.0039x over previous
#include <cuda_runtime.h>
#include <cuda_fp16.h>
#include <cuda_bf16.h>
#include <cstdint>
#include <cstddef>

// ---------------- problem constants ----------------
#define Bb   2
#define Ss   2048
#define Hh   4096
#define NHh  32
#define HDd  128
#define QKVN 12288            // NH * 3 * HD
#define Mm   4096             // B * S

#define QSCALE 0.08838834764831845f

// ---------------- scratch (__device__ globals; no allocs allowed) ----------
__device__ __half g_attn[(size_t)Mm * Hh];     // flash out, A-frag half
__device__ __half g_hid [(size_t)Mm * Hh];     // hidden, A-frag half
__device__ __half g_w1t [(size_t)QKVN * Hh];   // w_qkv, B-frag half
__device__ __half g_w2t [(size_t)Hh * Hh];     // w_out, B-frag half
// flash-ready fragment buffers written by GEMM1:
__device__ uint4 g_qf[(size_t)NHh * 256 * 8 * 32];
__device__ uint2 g_kf[(size_t)NHh * 512 * 8 * 32];
__device__ uint2 g_vf[(size_t)NHh * 64 * 4 * 16 * 32];

// ---------------- helpers ----------------
__device__ __forceinline__ uint32_t smem_u32(const void* p) {
    uint32_t a;
    asm("{ .reg .u64 t; cvta.to.shared.u64 t, %1; cvt.u32.u64 %0, t; }" : "=r"(a) : "l"(p));
    return a;
}
__device__ __forceinline__ uint32_t pkh2(float a, float b) {
    __half2 h = __floats2half2_rn(a, b);
    return *(uint32_t*)&h;
}
#define CP_ASYNC16(dst, src) \
    asm volatile("cp.async.cg.shared.global [%0], [%1], 16;" :: "r"(dst), "l"(src))
#define CP_COMMIT() asm volatile("cp.async.commit_group;")

__device__ __forceinline__ void mma_f16(float* d, const uint32_t* a, const uint32_t* b) {
    asm volatile(
        "mma.sync.aligned.m16n8k16.row.col.f32.f16.f16.f32 "
        "{%0,%1,%2,%3}, {%4,%5,%6,%7}, {%8,%9}, {%0,%1,%2,%3};"
        : "+f"(d[0]), "+f"(d[1]), "+f"(d[2]), "+f"(d[3])
        : "r"(a[0]), "r"(a[1]), "r"(a[2]), "r"(a[3]), "r"(b[0]), "r"(b[1]));
}

// fast exp on the FMA pipe (no MUFU)
__device__ __forceinline__ float fexp(float x) {
    x = fmaxf(x, -80.0f);
    float y = x * 1.4426950408889634f;
    int   n = __float2int_rn(y);
    float f = y - (float)n;
    float p = 1.33335581e-3f;
    p = fmaf(p, f, 9.61812911e-3f);
    p = fmaf(p, f, 5.55041087e-2f);
    p = fmaf(p, f, 2.40226507e-1f);
    p = fmaf(p, f, 6.93147181e-1f);
    p = fmaf(p, f, 1.0f);
    return p * __int_as_float((n + 127) << 23);
}

extern __shared__ float dynsm[];

// ---------------------------------------------------------------------------
// fp16 GEMM — NSTG=3, BKA=4, 64 iters, 48KB smem (2 CTAs/SM), and ONE
// __syncthreads per iteration:
//   prologue fills 2 stages; iteration it computes stage it%3 and fills
//   stage (it+2)%3 (the one consumed at it-1; the top-of-iteration barrier
//   proves it is drained). wait_group(1) at the top guarantees the current
//   stage's fill group completed (only data it+1 may be pending).
// QKV=true: emit flash-ready Q/K/V fragments. QKV=false: natural C + bias.
// ---------------------------------------------------------------------------
#define NSTG 3
#define BKA 4
#define A_STG_BYTES (8 * BKA * 512)    // 16KB
#define B_STG_BYTES (16 * BKA * 256)   // 16KB
#define STG_BYTES (A_STG_BYTES + B_STG_BYTES)
#define GEMM_SMEM (NSTG * STG_BYTES)

template<bool QKV>
__global__ __launch_bounds__(128) void gemm_mma_kernel(
    const void* __restrict__ Af, const void* __restrict__ Bf,
    const float* __restrict__ bias, float* __restrict__ C,
    int M, int N, int K)
{
    const int K16 = K >> 4;
    const int tid = threadIdx.x, lane = tid & 31, w = tid >> 5;
    const int wm = w >> 1, wn = w & 1;

    const int NT = N >> 7;
    const int per = 8 * NT;
    const int gg = blockIdx.x / per, rr = blockIdx.x % per;
    const int mtile = gg * 8 + (rr & 7);
    const int ntile = rr >> 3;

    const char* Ag = (const char*)Af + (size_t)mtile * 8 * K16 * 512;
    const char* Bg = (const char*)Bf + (size_t)ntile * 16 * K16 * 256;

    const uint32_t sb = smem_u32(dynsm);

    // ---- hoisted per-thread chunk bases (loop-invariant) ----
    const char* aBase[8];
    const char* bBase[8];
    #pragma unroll
    for (int i = 0; i < 8; i++) {
        int c = tid + i * 128;
        int mi = c >> 7, ra = c & 127;
        aBase[i] = Ag + (((size_t)mi * K16 + (ra >> 5)) * 32 + (ra & 31)) * 16;
        int ni = c >> 6, rb = c & 63;
        bBase[i] = Bg + ((size_t)ni * K16 + (rb >> 4)) * 256 + (rb & 15) * 16;
    }
    // advancing kt0 by 1 moves A source by 512 bytes, B by 256 bytes.

    auto fill = [&](int s, int kt0) {
        const uint32_t sA = sb + s * STG_BYTES;
        const uint32_t sB = sA + A_STG_BYTES;
        const size_t aAdv = (size_t)kt0 * 512;
        const size_t bAdv = (size_t)kt0 * 256;
        #pragma unroll
        for (int i = 0; i < 8; i++) CP_ASYNC16(sA + (tid + i * 128) * 16, aBase[i] + aAdv);
        #pragma unroll
        for (int i = 0; i < 8; i++) CP_ASYNC16(sB + (tid + i * 128) * 16, bBase[i] + bAdv);
        CP_COMMIT();
    };

    float acc[4][8][4];
    #pragma unroll
    for (int a = 0; a < 4; a++)
        #pragma unroll
        for (int b = 0; b < 8; b++)
            #pragma unroll
            for (int e = 0; e < 4; e++) acc[a][b][e] = 0.0f;

    const int NITER = K16 / BKA;      // 64 for K=4096
    // prologue: fill NSTG-1 = 2 stages (data 0, 1)
    #pragma unroll
    for (int s = 0; s < NSTG - 1; s++) fill(s, s * BKA);

    char* smp = (char*)dynsm;
    int s = 0;
    for (int it = 0; it < NITER; it++) {
        char* sA = smp + s * STG_BYTES;
        char* sB = sA + A_STG_BYTES;

        // only the newest group (data it+1) may be pending => data it ready
        asm volatile("cp.async.wait_group %0;" :: "n"(NSTG - 2));
        __syncthreads();

        #pragma unroll
        for (int ki = 0; ki < BKA; ki++) {
            uint32_t afr[4][4];
            #pragma unroll
            for (int a = 0; a < 4; a++) {
                uint4 v = *(const uint4*)(sA + (((wm * 4 + a) * BKA + ki) * 32 + lane) * 16);
                afr[a][0] = v.x; afr[a][1] = v.y; afr[a][2] = v.z; afr[a][3] = v.w;
            }
            uint32_t bfr[8][2];
            #pragma unroll
            for (int b = 0; b < 8; b++) {
                uint2 v = *(const uint2*)(sB + (((wn * 8 + b) * BKA + ki) * 32 + lane) * 8);
                bfr[b][0] = v.x; bfr[b][1] = v.y;
            }
            #pragma unroll
            for (int a = 0; a < 4; a++)
                #pragma unroll
                for (int b = 0; b < 8; b++)
                    mma_f16(acc[a][b], afr[a], bfr[b]);
        }

        // fill stage consumed last iteration ((s+2)%3) with data it+2.
        // Safe: this iteration's top barrier proved it is drained.
        if (it + NSTG - 1 < NITER) {
            int ns = s + NSTG - 1; if (ns >= NSTG) ns -= NSTG;
            fill(ns, (it + NSTG - 1) * BKA);
        } else CP_COMMIT();

        s = (s == NSTG - 1) ? 0 : s + 1;
    }
    __syncthreads();   // all compute done before epilogue may reuse SMEM

    const int c2 = (lane & 3) * 2;

    if (QKV) {
        const int h = ntile / 3, sec = ntile % 3;
        const int cbase = ntile * 128 + wn * 64;
        if (sec == 0) {
            // ---- Q: (acc+bias)*QSCALE -> A-frags, pure register pack ----
            #pragma unroll
            for (int a = 0; a < 4; a++) {
                size_t mi = (size_t)mtile * 8 + wm * 4 + a;
                #pragma unroll
                for (int j = 0; j < 4; j++) {
                    int ka = wn * 4 + j;
                    float2 bv0 = *(const float2*)(bias + cbase + (2 * j) * 8 + c2);
                    float2 bv1 = *(const float2*)(bias + cbase + (2 * j + 1) * 8 + c2);
                    uint4 u;
                    u.x = pkh2((acc[a][2*j][0] + bv0.x) * QSCALE, (acc[a][2*j][1] + bv0.y) * QSCALE);
                    u.y = pkh2((acc[a][2*j][2] + bv0.x) * QSCALE, (acc[a][2*j][3] + bv0.y) * QSCALE);
                    u.z = pkh2((acc[a][2*j+1][0] + bv1.x) * QSCALE, (acc[a][2*j+1][1] + bv1.y) * QSCALE);
                    u.w = pkh2((acc[a][2*j+1][2] + bv1.x) * QSCALE, (acc[a][2*j+1][3] + bv1.y) * QSCALE);
                    g_qf[(((size_t)h * 256 + mi) * 8 + ka) * 32 + lane] = u;
                }
            }
        } else if (sec == 1) {
            // ---- K: acc+bias -> B-frags (n=key, k=d), pure register pack ----
            #pragma unroll
            for (int a = 0; a < 4; a++) {
                size_t na0 = (size_t)mtile * 16 + wm * 8 + a * 2;
                #pragma unroll
                for (int j = 0; j < 4; j++) {
                    int ka = wn * 4 + j;
                    float2 bv0 = *(const float2*)(bias + cbase + (2 * j) * 8 + c2);
                    float2 bv1 = *(const float2*)(bias + cbase + (2 * j + 1) * 8 + c2);
                    uint2 u0, u1;
                    u0.x = pkh2(acc[a][2*j][0] + bv0.x,   acc[a][2*j][1] + bv0.y);
                    u0.y = pkh2(acc[a][2*j+1][0] + bv1.x, acc[a][2*j+1][1] + bv1.y);
                    u1.x = pkh2(acc[a][2*j][2] + bv0.x,   acc[a][2*j][3] + bv0.y);
                    u1.y = pkh2(acc[a][2*j+1][2] + bv1.x, acc[a][2*j+1][3] + bv1.y);
                    g_kf[(((size_t)h * 512 + na0)     * 8 + ka) * 32 + lane] = u0;
                    g_kf[(((size_t)h * 512 + na0 + 1) * 8 + ka) * 32 + lane] = u1;
                }
            }
        } else {
            // ---- V: SMEM bounce transpose -> B-frags (n=d, k=key) ----
            __half* sv = (__half*)dynsm;          // [128 keys][136 d halves]
            #pragma unroll
            for (int a = 0; a < 4; a++) {
                int r = wm * 64 + a * 16 + (lane >> 2);
                #pragma unroll
                for (int b = 0; b < 8; b++) {
                    int c = wn * 64 + b * 8 + c2;
                    float2 bv = *(const float2*)(bias + ntile * 128 + c);
                    *(uint32_t*)&sv[r * 136 + c]       = pkh2(acc[a][b][0] + bv.x, acc[a][b][1] + bv.y);
                    *(uint32_t*)&sv[(r + 8) * 136 + c] = pkh2(acc[a][b][2] + bv.x, acc[a][b][3] + bv.y);
                }
            }
            __syncthreads();
            const uint16_t* sh = (const uint16_t*)dynsm;
            #pragma unroll
            for (int i = 0; i < 32; i++) {
                int blk = w + i * 4;                     // 0..127
                int t2 = blk >> 6, rem = blk & 63;
                int ka4 = rem >> 4, na = rem & 15;
                int d  = na * 8 + (lane >> 2);
                int kl = t2 * 64 + ka4 * 16 + c2;
                uint32_t x0 = sh[kl * 136 + d],       x1 = sh[(kl + 1) * 136 + d];
                uint32_t x2 = sh[(kl + 8) * 136 + d], x3 = sh[(kl + 9) * 136 + d];
                uint2 u; u.x = x0 | (x1 << 16); u.y = x2 | (x3 << 16);
                size_t g = (size_t)mtile * 2 + t2;       // = b*32 + kt
                g_vf[((((size_t)h * 64 + g) * 4 + ka4) * 16 + na) * 32 + lane] = u;
            }
        }
        return;
    }

    // ---- natural epilogue (GEMM2) ----
    const size_t row0 = (size_t)mtile * 128 + wm * 64 + (lane >> 2);
    const int col0 = ntile * 128 + wn * 64 + c2;
    #pragma unroll
    for (int a = 0; a < 4; a++) {
        #pragma unroll
        for (int b = 0; b < 8; b++) {
            int c = col0 + b * 8;
            float2 bv = *(const float2*)(bias + c);
            size_t r = row0 + a * 16;
            float2 o0; o0.x = acc[a][b][0] + bv.x; o0.y = acc[a][b][1] + bv.y;
            *(float2*)(C + r * N + c) = o0;
            float2 o1; o1.x = acc[a][b][2] + bv.x; o1.y = acc[a][b][3] + bv.y;
            *(float2*)(C + (r + 8) * N + c) = o1;
        }
    }
}

// ---------------------------------------------------------------------------
// prep: fragmentize to half (unchanged)
// ---------------------------------------------------------------------------
__global__ __launch_bounds__(128) void frag_a_kernel(
    const float* __restrict__ src, __half* __restrict__ dst, int K)
{
    __shared__ float t[32][33];
    const int k0 = blockIdx.x * 32, m0 = blockIdx.y * 32;
    const int tid = threadIdx.x;
    #pragma unroll
    for (int i = 0; i < 8; i++) {
        int idx = tid + i * 128;
        int r = idx >> 5, c = idx & 31;
        t[r][c] = src[(size_t)(m0 + r) * K + k0 + c];
    }
    __syncthreads();
    const int w = tid >> 5, lane = tid & 31;
    const int mi_l = w >> 1, ki_l = w & 1;
    const int r0 = mi_l * 16 + (lane >> 2);
    const int c0 = ki_l * 16 + (lane & 3) * 2;
    uint4 u;
    u.x = pkh2(t[r0][c0],         t[r0][c0 + 1]);
    u.y = pkh2(t[r0 + 8][c0],     t[r0 + 8][c0 + 1]);
    u.z = pkh2(t[r0][c0 + 8],     t[r0][c0 + 9]);
    u.w = pkh2(t[r0 + 8][c0 + 8], t[r0 + 8][c0 + 9]);
    ((uint4*)dst)[((size_t)((m0 >> 4) + mi_l) * (K >> 4) + (k0 >> 4) + ki_l) * 32 + lane] = u;
}

__global__ __launch_bounds__(256) void frag_b_kernel(
    const float* __restrict__ src, __half* __restrict__ dst, int K, int N)
{
    __shared__ float t[32][33];
    const int n0 = blockIdx.x * 32, k0 = blockIdx.y * 32;
    const int tid = threadIdx.x;
    #pragma unroll
    for (int i = 0; i < 4; i++) {
        int r = (tid >> 5) + i * 8;
        t[r][tid & 31] = src[(size_t)(k0 + r) * N + n0 + (tid & 31)];
    }
    __syncthreads();
    const int w = tid >> 5, lane = tid & 31;
    const int ni_l = w >> 1, ki_l = w & 1;
    const int n = ni_l * 8 + (lane >> 2);
    const int k = ki_l * 16 + (lane & 3) * 2;
    uint2 u;
    u.x = pkh2(t[k][n],     t[k + 1][n]);
    u.y = pkh2(t[k + 8][n], t[k + 9][n]);
    ((uint2*)dst)[((size_t)((n0 >> 3) + ni_l) * (K >> 4) + (k0 >> 4) + ki_l) * 32 + lane] = u;
}

// ---------------------------------------------------------------------------
// Flash attention: pre-formatted half fragments, cp.async double-buffered.
// LPT scheduling: qt REVERSED vs blockIdx so heaviest CTAs launch first.
// (unchanged from round 16)
// ---------------------------------------------------------------------------
#define FL_STG 32768
#define FLASH_SMEM_B (2 * FL_STG + 768)

__global__ __launch_bounds__(128) void flash_mma_kernel(
    const float* __restrict__ alibi, const int* __restrict__ amask,
    __half* __restrict__ attn_out)
{
    const int qt = gridDim.x - 1 - blockIdx.x;   // longest-job-first
    const int h = blockIdx.y, bb = blockIdx.z;
    const int qb = qt * 64;
    const int tid = threadIdx.x, lane = tid & 31, w = tid >> 5;
    const int c2 = (lane & 3) * 2;

    const uint32_t sb = smem_u32(dynsm);
    float* sAl = (float*)((char*)dynsm + 2 * FL_STG);

    const float* alib = alibi + ((size_t)bb * NHh + h) * Ss;
    const int* amk = amask + (size_t)bb * Ss;

    auto fill = [&](int s, int kt) {
        const char* Ks = (const char*)(g_kf + (((size_t)h * 512 + bb * 256 + (size_t)kt * 8) * 8) * 32);
        const char* Vs = (const char*)(g_vf + ((((size_t)h * 64 + bb * 32 + kt) * 4) * 16) * 32);
        uint32_t sK = sb + s * FL_STG;
        uint32_t sV = sK + 16384;
        #pragma unroll
        for (int i = 0; i < 8; i++) {
            int c = (tid + i * 128) * 16;
            CP_ASYNC16(sK + c, Ks + c);
            CP_ASYNC16(sV + c, Vs + c);
        }
        CP_COMMIT();
    };

    fill(0, 0);

    uint32_t qf[8][4];
    {
        size_t mi = (size_t)bb * 128 + qt * 4 + w;
        const uint4* qsrc = g_qf + ((size_t)h * 256 + mi) * 8 * 32 + lane;
        #pragma unroll
        for (int ka = 0; ka < 8; ka++) {
            uint4 v = qsrc[ka * 32];
            qf[ka][0] = v.x; qf[ka][1] = v.y; qf[ka][2] = v.z; qf[ka][3] = v.w;
        }
    }

    float m0 = -1e29f, m1 = -1e29f, l0 = 0.0f, l1 = 0.0f;
    float acc[16][4];
    #pragma unroll
    for (int na = 0; na < 16; na++)
        #pragma unroll
        for (int e = 0; e < 4; e++) acc[na][e] = 0.0f;

    const int qg0 = qb + w * 16 + (lane >> 2);
    const int qg1 = qg0 + 8;

    for (int kt = 0; kt <= qt; kt++) {
        const int cur = kt & 1;
        const int kb = kt * 64;

        if (kt < qt) fill(cur ^ 1, kt + 1);
        else CP_COMMIT();

        asm volatile("cp.async.wait_group %0;" :: "n"(1));
        if (tid < 64) {
            int kg = kb + tid;
            sAl[cur * 96 + tid] = (amk[kg] > 0) ? alib[kg] : -1e30f;
        }
        __syncthreads();

        const uint2* Kf2 = (const uint2*)((char*)dynsm + cur * FL_STG);
        const uint2* Vf2 = (const uint2*)((char*)dynsm + cur * FL_STG + 16384);
        const float* sAc = sAl + cur * 96;

        float sfr[8][4];
        #pragma unroll
        for (int na = 0; na < 8; na++)
            #pragma unroll
            for (int e = 0; e < 4; e++) sfr[na][e] = 0.0f;

        #pragma unroll
        for (int ka = 0; ka < 8; ka++) {
            #pragma unroll
            for (int na = 0; na < 8; na++) {
                uint2 bv = Kf2[(na * 8 + ka) * 32 + lane];
                uint32_t br[2] = {bv.x, bv.y};
                mma_f16(sfr[na], qf[ka], br);
            }
        }

        const bool diag = (kt == qt);
        float tm0 = -1e30f, tm1 = -1e30f;
        #pragma unroll
        for (int na = 0; na < 8; na++) {
            int c0 = na * 8 + c2;
            int kg0 = kb + c0;
            float al0 = sAc[c0], al1 = sAc[c0 + 1];
            if (diag) {
                sfr[na][0] = (kg0     <= qg0) ? sfr[na][0] + al0 : -1e30f;
                sfr[na][1] = (kg0 + 1 <= qg0) ? sfr[na][1] + al1 : -1e30f;
                sfr[na][2] = (kg0     <= qg1) ? sfr[na][2] + al0 : -1e30f;
                sfr[na][3] = (kg0 + 1 <= qg1) ? sfr[na][3] + al1 : -1e30f;
            } else {
                sfr[na][0] += al0; sfr[na][1] += al1;
                sfr[na][2] += al0; sfr[na][3] += al1;
            }
            tm0 = fmaxf(tm0, fmaxf(sfr[na][0], sfr[na][1]));
            tm1 = fmaxf(tm1, fmaxf(sfr[na][2], sfr[na][3]));
        }
        tm0 = fmaxf(tm0, __shfl_xor_sync(0xffffffffu, tm0, 1));
        tm0 = fmaxf(tm0, __shfl_xor_sync(0xffffffffu, tm0, 2));
        tm1 = fmaxf(tm1, __shfl_xor_sync(0xffffffffu, tm1, 1));
        tm1 = fmaxf(tm1, __shfl_xor_sync(0xffffffffu, tm1, 2));

        float mn0 = fmaxf(m0, tm0), mn1 = fmaxf(m1, tm1);
        float corr0 = fexp(m0 - mn0), corr1 = fexp(m1 - mn1);

        float rs0 = 0.0f, rs1 = 0.0f;
        #pragma unroll
        for (int na = 0; na < 8; na++) {
            sfr[na][0] = fexp(sfr[na][0] - mn0);
            sfr[na][1] = fexp(sfr[na][1] - mn0);
            sfr[na][2] = fexp(sfr[na][2] - mn1);
            sfr[na][3] = fexp(sfr[na][3] - mn1);
            rs0 += sfr[na][0] + sfr[na][1];
            rs1 += sfr[na][2] + sfr[na][3];
        }
        rs0 += __shfl_xor_sync(0xffffffffu, rs0, 1);
        rs0 += __shfl_xor_sync(0xffffffffu, rs0, 2);
        rs1 += __shfl_xor_sync(0xffffffffu, rs1, 1);
        rs1 += __shfl_xor_sync(0xffffffffu, rs1, 2);
        l0 = l0 * corr0 + rs0;  m0 = mn0;
        l1 = l1 * corr1 + rs1;  m1 = mn1;
        #pragma unroll
        for (int na = 0; na < 16; na++) {
            acc[na][0] *= corr0; acc[na][1] *= corr0;
            acc[na][2] *= corr1; acc[na][3] *= corr1;
        }

        uint32_t pa[4][4];
        #pragma unroll
        for (int j = 0; j < 4; j++) {
            pa[j][0] = pkh2(sfr[2 * j][0],     sfr[2 * j][1]);
            pa[j][1] = pkh2(sfr[2 * j][2],     sfr[2 * j][3]);
            pa[j][2] = pkh2(sfr[2 * j + 1][0], sfr[2 * j + 1][1]);
            pa[j][3] = pkh2(sfr[2 * j + 1][2], sfr[2 * j + 1][3]);
        }

        #pragma unroll
        for (int ka4 = 0; ka4 < 4; ka4++) {
            #pragma unroll
            for (int na = 0; na < 16; na++) {
                uint2 bv = Vf2[(ka4 * 16 + na) * 32 + lane];
                uint32_t br[2] = {bv.x, bv.y};
                mma_f16(acc[na], pa[ka4], br);
            }
        }
        __syncthreads();
    }

    {
        float inv0 = 1.0f / fmaxf(l0, 1e-30f);
        float inv1 = 1.0f / fmaxf(l1, 1e-30f);
        size_t mi = (size_t)(bb * Ss + qb + w * 16) >> 4;
        uint4* ao = (uint4*)attn_out;
        #pragma unroll
        for (int j = 0; j < 8; j++) {
            uint4 u;
            u.x = pkh2(acc[2 * j][0] * inv0,     acc[2 * j][1] * inv0);
            u.y = pkh2(acc[2 * j][2] * inv1,     acc[2 * j][3] * inv1);
            u.z = pkh2(acc[2 * j + 1][0] * inv0, acc[2 * j + 1][1] * inv0);
            u.w = pkh2(acc[2 * j + 1][2] * inv1, acc[2 * j + 1][3] * inv1);
            ao[(mi * 256 + (size_t)h * 8 + j) * 32 + lane] = u;
        }
    }
}

// ---------------------------------------------------------------------------
extern "C" void kernel_launch(void* const* d_in, const int* in_sizes, int n_in,
                              void* d_out, int out_size)
{
    const float* hidden = (const float*)d_in[0];
    const float* alibi  = (const float*)d_in[1];
    const float* w_qkv  = (const float*)d_in[2];
    const float* b_qkv  = (const float*)d_in[3];
    const float* w_out  = (const float*)d_in[4];
    const float* b_out  = (const float*)d_in[5];
    const int*   amask  = (const int*)d_in[6];
    float* out = (float*)d_out;

    __half *attn, *hid, *w1t, *w2t;
    cudaGetSymbolAddress((void**)&attn, g_attn);
    cudaGetSymbolAddress((void**)&hid,  g_hid);
    cudaGetSymbolAddress((void**)&w1t,  g_w1t);
    cudaGetSymbolAddress((void**)&w2t,  g_w2t);

    cudaFuncSetAttribute(gemm_mma_kernel<true>,
                         cudaFuncAttributeMaxDynamicSharedMemorySize, GEMM_SMEM);
    cudaFuncSetAttribute(gemm_mma_kernel<false>,
                         cudaFuncAttributeMaxDynamicSharedMemorySize, GEMM_SMEM);
    cudaFuncSetAttribute(flash_mma_kernel,
                         cudaFuncAttributeMaxDynamicSharedMemorySize, FLASH_SMEM_B);

    // prep: fragmentize to half
    frag_a_kernel<<<dim3(Hh / 32, Mm / 32), 128>>>(hidden, hid, Hh);
    frag_b_kernel<<<dim3(QKVN / 32, Hh / 32), 256>>>(w_qkv, w1t, Hh, QKVN);
    frag_b_kernel<<<dim3(Hh / 32, Hh / 32), 256>>>(w_out, w2t, Hh, Hh);

    // 1) QKV projection -> flash-ready Q/K/V fragment buffers
    gemm_mma_kernel<true><<<(Mm / 128) * (QKVN / 128), 128, GEMM_SMEM>>>(
        hid, w1t, b_qkv, nullptr, Mm, QKVN, Hh);

    // 2) flash attention (pure cp.async + fp16 mma, LPT-ordered)
    flash_mma_kernel<<<dim3(Ss / 64, NHh, Bb), 128, FLASH_SMEM_B>>>(
        alibi, amask, attn);

    // 3) output projection
    gemm_mma_kernel<false><<<(Mm / 128) * (Hh / 128), 128, GEMM_SMEM>>>(
        attn, w2t, b_out, out, Mm, Hh, Hh);
}